// round 2
// baseline (speedup 1.0000x reference)
#include <cuda_runtime.h>
#include <math.h>

#define HH   1024
#define II   256
#define BB   64
#define TT   512
#define G4   4096              // 4*H
#define MM   (BB*TT)           // 32768

#define NCTA      128          // persistent grid: 1 CTA/SM, <= SM count (safe co-residency)
#define UPC       8            // hidden units per CTA (128*8 = 1024)
#define LCOLS     32           // 4 gates * UPC local output columns
#define BK        32           // K tile for recurrent GEMM

// ---------------- scratch (static device globals; no allocation) ----------------
__device__ float g_xg[(size_t)MM * G4];      // [B*T, 4H] input projection (+b_ih)
__device__ float g_hs[(size_t)TT * BB * HH]; // [T, B, H] hidden history

// ---------------- device-wide barrier state (self-resetting across replays) -----
__device__ unsigned          g_bar_count = 0;
__device__ volatile unsigned g_bar_gen   = 0;

// =====================================================================
// Kernel 1: xg[m][n] = sum_k x[m][k] * W_ih[n][k] + b_ih[n]
// M=32768, N=4096, K=256.  BM=128 BN=64 BK=16, 256 thr, micro 8x4.
// =====================================================================
__global__ __launch_bounds__(256) void xg_gemm(const float* __restrict__ x,
                                               const float* __restrict__ Wih,
                                               const float* __restrict__ bih)
{
    const int BM = 128, BN = 64, BKi = 16;
    __shared__ float As[2][BKi][BM + 4];
    __shared__ float Ws[2][BKi][BN + 4];

    const int n0  = blockIdx.x * BN;
    const int m0  = blockIdx.y * BM;
    const int tid = threadIdx.x;
    const int tr  = tid / 16;
    const int tc  = tid % 16;

    const int a_row0 = (tid)       >> 2, a_kq0 = (tid)       & 3;
    const int a_row1 = (tid + 256) >> 2, a_kq1 = (tid + 256) & 3;
    const int w_row  = tid >> 2,         w_kq  = tid & 3;

    float acc[8][4];
#pragma unroll
    for (int i = 0; i < 8; i++)
#pragma unroll
        for (int j = 0; j < 4; j++) acc[i][j] = 0.f;

    float4 a0, a1, wv;

#define XG_LOADG(it)                                                               \
    {   int k0 = (it) * BKi;                                                       \
        a0 = *(const float4*)&x[(size_t)(m0 + a_row0) * II + k0 + a_kq0 * 4];      \
        a1 = *(const float4*)&x[(size_t)(m0 + a_row1) * II + k0 + a_kq1 * 4];      \
        wv = *(const float4*)&Wih[(size_t)(n0 + w_row) * II + k0 + w_kq * 4];      \
    }
#define XG_STORE(buf)                                                              \
    {   As[buf][a_kq0*4+0][a_row0] = a0.x; As[buf][a_kq0*4+1][a_row0] = a0.y;      \
        As[buf][a_kq0*4+2][a_row0] = a0.z; As[buf][a_kq0*4+3][a_row0] = a0.w;      \
        As[buf][a_kq1*4+0][a_row1] = a1.x; As[buf][a_kq1*4+1][a_row1] = a1.y;      \
        As[buf][a_kq1*4+2][a_row1] = a1.z; As[buf][a_kq1*4+3][a_row1] = a1.w;      \
        Ws[buf][w_kq*4+0][w_row]   = wv.x; Ws[buf][w_kq*4+1][w_row]   = wv.y;      \
        Ws[buf][w_kq*4+2][w_row]   = wv.z; Ws[buf][w_kq*4+3][w_row]   = wv.w;      \
    }

    XG_LOADG(0); XG_STORE(0); __syncthreads();

    const int NIT = II / BKi; // 16
    for (int it = 0; it < NIT; it++) {
        const int cur = it & 1;
        if (it + 1 < NIT) XG_LOADG(it + 1);
#pragma unroll
        for (int kk = 0; kk < BKi; kk++) {
            float a[8], w[4];
#pragma unroll
            for (int i = 0; i < 8; i++) a[i] = As[cur][kk][tr * 8 + i];
#pragma unroll
            for (int j = 0; j < 4; j++) w[j] = Ws[cur][kk][tc * 4 + j];
#pragma unroll
            for (int i = 0; i < 8; i++)
#pragma unroll
                for (int j = 0; j < 4; j++) acc[i][j] += a[i] * w[j];
        }
        if (it + 1 < NIT) XG_STORE(cur ^ 1);
        __syncthreads();
    }

    const float4 bv = *(const float4*)&bih[n0 + tc * 4];
#pragma unroll
    for (int i = 0; i < 8; i++) {
        const size_t row = (size_t)(m0 + tr * 8 + i);
        float4 o;
        o.x = acc[i][0] + bv.x; o.y = acc[i][1] + bv.y;
        o.z = acc[i][2] + bv.z; o.w = acc[i][3] + bv.w;
        *(float4*)&g_xg[row * G4 + (n0 + tc * 4)] = o;
    }
}

// =====================================================================
// Kernel 2: persistent LSTM recurrence. 128 CTAs x 256 threads.
// CTA owns 8 hidden units -> 32 output columns (i,f,g,o x 8).
// W_hh slice (32 x 1024 = 128 KB) lives in smem for all 512 steps.
// Cell state c lives in smem. One device-wide barrier per step.
// =====================================================================
__device__ __forceinline__ void grid_sync_()
{
    __threadfence();           // release h writes
    __syncthreads();
    if (threadIdx.x == 0) {
        const unsigned gen = g_bar_gen;
        if (atomicAdd(&g_bar_count, 1u) == (unsigned)gridDim.x - 1u) {
            g_bar_count = 0;
            __threadfence();
            g_bar_gen = gen + 1u;
        } else {
            while (g_bar_gen == gen) { __nanosleep(64); }
        }
        __threadfence();       // acquire
    }
    __syncthreads();
}

// dynamic smem layout (floats):
//   Wk [1024][32]      32768
//   Hs [2][BK][64]      4096
//   Gs [64][32]         2048
//   Cs [64][8]           512
//   Bh [32]               32
#define SM_WK   0
#define SM_HS   (SM_WK + 1024 * 32)
#define SM_GS   (SM_HS + 2 * BK * 64)
#define SM_CS   (SM_GS + 64 * 32)
#define SM_BH   (SM_CS + 64 * 8)
#define SM_TOTF (SM_BH + 32)
#define SMEM_BYTES (SM_TOTF * 4)

__global__ __launch_bounds__(256) void lstm_persistent(const float* __restrict__ Whh,
                                                       const float* __restrict__ bhh)
{
    extern __shared__ float sm[];
    float* Wk = sm + SM_WK;
    float* Hs = sm + SM_HS;
    float* Gs = sm + SM_GS;
    float* Cs = sm + SM_CS;
    float* Bh = sm + SM_BH;

    const int tid  = threadIdx.x;
    const int warp = tid >> 5;
    const int lane = tid & 31;
    const int u0   = blockIdx.x * UPC;

    // local col c in 0..31: gate = c/8, unit = u0 + c%8 -> global col gate*1024 + u0 + c%8
    // ---- one-time: load W_hh slice into smem, k-major (Wk[k][c]) ----
    {
        const int c    = lane;                       // conflict-free STS (bank = lane)
        const int gcol = (c >> 3) * HH + u0 + (c & 7);
        const float* __restrict__ wrow = Whh + (size_t)gcol * HH;
#pragma unroll 4
        for (int q = 0; q < 32; q++) {
            const int k = warp * 128 + q * 4;
            const float4 v = *(const float4*)&wrow[k];
            Wk[(k + 0) * LCOLS + c] = v.x;
            Wk[(k + 1) * LCOLS + c] = v.y;
            Wk[(k + 2) * LCOLS + c] = v.z;
            Wk[(k + 3) * LCOLS + c] = v.w;
        }
    }
    if (tid < LCOLS) Bh[tid] = bhh[(tid >> 3) * HH + u0 + (tid & 7)];
    for (int i = tid; i < 64 * UPC; i += 256) Cs[i] = 0.f;
    __syncthreads();

    // micro-tile mapping: tr = batch group (4 rows), tc = col pair
    const int tr = tid >> 4;   // 0..15
    const int tc = tid & 15;   // 0..15
    // tile-load mapping: bq = batch, kq = k-subchunk of 8
    const int bq = tid & 63;
    const int kq = tid >> 6;   // 0..3

    // pointwise mapping: b, unit pair
    const int pb = tid >> 2;        // 0..63
    const int pu = (tid & 3) * 2;   // 0,2,4,6

    for (int t = 0; t < TT; t++) {
        float acc[4][2];
#pragma unroll
        for (int i = 0; i < 4; i++) { acc[i][0] = 0.f; acc[i][1] = 0.f; }

        if (t > 0) {
            const float* __restrict__ hprev = g_hs + (size_t)(t - 1) * BB * HH;
            float4 r0, r1;
            // prologue: tile 0 -> buf 0
            {
                const float* hp = hprev + (size_t)bq * HH + kq * 8;
                r0 = *(const float4*)hp; r1 = *(const float4*)(hp + 4);
                float* d = &Hs[(0 * BK + kq * 8) * 64 + bq];
                d[0*64]=r0.x; d[1*64]=r0.y; d[2*64]=r0.z; d[3*64]=r0.w;
                d[4*64]=r1.x; d[5*64]=r1.y; d[6*64]=r1.z; d[7*64]=r1.w;
            }
            __syncthreads();

            const int NKT = HH / BK;  // 32
            for (int kt = 0; kt < NKT; kt++) {
                const int buf = kt & 1;
                if (kt + 1 < NKT) {
                    const float* hp = hprev + (size_t)bq * HH + (kt + 1) * BK + kq * 8;
                    r0 = *(const float4*)hp; r1 = *(const float4*)(hp + 4);
                }
#pragma unroll
                for (int kk = 0; kk < BK; kk++) {
                    const float4 a = *(const float4*)&Hs[(buf * BK + kk) * 64 + tr * 4];
                    const float2 w = *(const float2*)&Wk[(kt * BK + kk) * LCOLS + tc * 2];
                    acc[0][0] += a.x * w.x;  acc[0][1] += a.x * w.y;
                    acc[1][0] += a.y * w.x;  acc[1][1] += a.y * w.y;
                    acc[2][0] += a.z * w.x;  acc[2][1] += a.z * w.y;
                    acc[3][0] += a.w * w.x;  acc[3][1] += a.w * w.y;
                }
                if (kt + 1 < NKT) {
                    float* d = &Hs[((buf ^ 1) * BK + kq * 8) * 64 + bq];
                    d[0*64]=r0.x; d[1*64]=r0.y; d[2*64]=r0.z; d[3*64]=r0.w;
                    d[4*64]=r1.x; d[5*64]=r1.y; d[6*64]=r1.z; d[7*64]=r1.w;
                }
                __syncthreads();
            }
        }

        // stash gates to smem for the CTA-local pointwise
#pragma unroll
        for (int i = 0; i < 4; i++)
            *(float2*)&Gs[(tr * 4 + i) * LCOLS + tc * 2] = *(float2*)&acc[i][0];
        __syncthreads();

        // ---- pointwise: each thread handles (pb, pu) and (pb, pu+1) ----
        {
            const size_t xbase = ((size_t)pb * TT + t) * G4 + u0 + pu;
            const float2 xi = *(const float2*)&g_xg[xbase];
            const float2 xf = *(const float2*)&g_xg[xbase + HH];
            const float2 xg2 = *(const float2*)&g_xg[xbase + 2 * HH];
            const float2 xo = *(const float2*)&g_xg[xbase + 3 * HH];

            const float2 ri = *(const float2*)&Gs[pb * LCOLS + 0  + pu];
            const float2 rf = *(const float2*)&Gs[pb * LCOLS + 8  + pu];
            const float2 rg = *(const float2*)&Gs[pb * LCOLS + 16 + pu];
            const float2 ro = *(const float2*)&Gs[pb * LCOLS + 24 + pu];

            const float2 cpr = *(const float2*)&Cs[pb * UPC + pu];

            float2 hv, cv;
#pragma unroll
            for (int s = 0; s < 2; s++) {
                const float gi = (s ? xi.y : xi.x) + (s ? ri.y : ri.x) + Bh[0  + pu + s];
                const float gf = (s ? xf.y : xf.x) + (s ? rf.y : rf.x) + Bh[8  + pu + s];
                const float gg = (s ? xg2.y : xg2.x) + (s ? rg.y : rg.x) + Bh[16 + pu + s];
                const float go = (s ? xo.y : xo.x) + (s ? ro.y : ro.x) + Bh[24 + pu + s];

                const float i_ = 1.f / (1.f + __expf(-gi) * 0.f + expf(-gi) * 1.f);
                const float f_ = 1.f / (1.f + expf(-gf));
                const float g_ = tanhf(gg);
                const float o_ = 1.f / (1.f + expf(-go));
                const float cp = (t > 0) ? (s ? cpr.y : cpr.x) : 0.f;
                const float c  = f_ * cp + i_ * g_;
                const float h  = o_ * tanhf(c);
                if (s) { cv.y = c; hv.y = h; } else { cv.x = c; hv.x = h; }
            }
            *(float2*)&Cs[pb * UPC + pu] = cv;
            *(float2*)&g_hs[((size_t)t * BB + pb) * HH + u0 + pu] = hv;
        }

        grid_sync_();
    }
}

// =====================================================================
// Kernel 3: out[b][t] = dot(h_t[b], W_fc) + b_fc.  One block per (t,b).
// =====================================================================
__global__ __launch_bounds__(128) void fc_kernel(const float* __restrict__ Wfc,
                                                 const float* __restrict__ bfc,
                                                 float* __restrict__ out)
{
    const int bt = blockIdx.x;
    const int t  = bt >> 6;
    const int b  = bt & 63;
    const float* __restrict__ h = g_hs + ((size_t)t * BB + b) * HH;
    const int tid = threadIdx.x;

    float s = 0.f;
#pragma unroll
    for (int q = 0; q < 8; q++) {
        const int j = tid + q * 128;
        s += h[j] * Wfc[j];
    }
#pragma unroll
    for (int off = 16; off; off >>= 1) s += __shfl_down_sync(0xffffffffu, s, off);

    __shared__ float red[4];
    if ((tid & 31) == 0) red[tid >> 5] = s;
    __syncthreads();
    if (tid == 0)
        out[(size_t)b * TT + t] = red[0] + red[1] + red[2] + red[3] + bfc[0];
}

// =====================================================================
extern "C" void kernel_launch(void* const* d_in, const int* in_sizes, int n_in,
                              void* d_out, int out_size)
{
    const float* x   = (const float*)d_in[0];
    const float* Wih = (const float*)d_in[1];
    const float* Whh = (const float*)d_in[2];
    const float* bih = (const float*)d_in[3];
    const float* bhh = (const float*)d_in[4];
    const float* Wfc = (const float*)d_in[5];
    const float* bfc = (const float*)d_in[6];
    float* out = (float*)d_out;

    cudaFuncSetAttribute(lstm_persistent,
                         cudaFuncAttributeMaxDynamicSharedMemorySize, SMEM_BYTES);

    // 1) input projection for all timesteps (one GEMM)
    xg_gemm<<<dim3(G4 / 64, MM / 128), 256>>>(x, Wih, bih);

    // 2) whole recurrence in ONE persistent kernel (device-wide barrier per step)
    lstm_persistent<<<NCTA, 256, SMEM_BYTES>>>(Whh, bhh);

    // 3) output projection
    fc_kernel<<<MM, 128>>>(Wfc, bfc, out);
}

// round 9
// speedup vs baseline: 1.5857x; 1.5857x over previous
#include <cuda_runtime.h>
#include <cuda_bf16.h>
#include <mma.h>
#include <math.h>

using namespace nvcuda;

// ---------------- compile-time constants (no object-like macros) ----------------
constexpr int HH = 1024;
constexpr int II = 256;
constexpr int BB = 64;
constexpr int TT = 512;
constexpr int G4 = 4096;                 // 4*H
constexpr int MM = BB * TT;              // 32768

constexpr int NCTA   = 128;              // persistent grid: 1 CTA/SM, co-resident
constexpr int APITCH = 72;               // A smem row pitch (bf16 elems), 144 B
constexpr int BPITCH = 1032;             // B smem row pitch (bf16 elems), 2064 B
constexpr int KCH    = 64;               // K chunk staged per iteration

// smem byte offsets for the persistent kernel
constexpr unsigned SMB_BSH = 0;                                   // 32*BPITCH bf16
constexpr unsigned SMB_BSL = SMB_BSH + 32u * BPITCH * 2u;         // 66048
constexpr unsigned SMB_ASH = SMB_BSL + 32u * BPITCH * 2u;         // 132096
constexpr unsigned SMB_ASL = SMB_ASH + 2u * 64u * APITCH * 2u;    // 150528
constexpr unsigned SMB_GS  = SMB_ASL + 2u * 64u * APITCH * 2u;    // 168960
constexpr unsigned SMB_CS  = SMB_GS + 64u * 40u * 4u;             // 179200
constexpr unsigned SMB_BH  = SMB_CS + 64u * 8u * 4u;              // 181248
constexpr unsigned SMB_TOT = SMB_BH + 32u * 4u;                   // 181376

// ---------------- scratch (static device globals; no allocation) ----------------
__device__ float         g_xg [(size_t)MM * G4];       // [B*T, 4H] x@W_ih^T + b_ih
__device__ __nv_bfloat16 g_hhi[(size_t)TT * BB * HH];  // h history, bf16 high part
__device__ __nv_bfloat16 g_hlo[(size_t)TT * BB * HH];  // h history, bf16 low part

// ---------------- device-wide barrier (self-resetting across graph replays) -----
__device__ unsigned          g_bar_count = 0;
__device__ volatile unsigned g_bar_gen   = 0;

// =====================================================================
// Kernel 1: xg[m][n] = sum_k x[m][k]*W_ih[n][k] + b_ih[n]   (fp32 SIMT)
// (structure identical to the round-2 version that compiled and passed)
// =====================================================================
__global__ __launch_bounds__(256) void xg_gemm(const float* __restrict__ x,
                                               const float* __restrict__ Wih,
                                               const float* __restrict__ bih)
{
    const int BM = 128, BN = 64, BKi = 16;
    __shared__ float As[2][16][BM + 4];
    __shared__ float Ws[2][16][BN + 4];

    const int n0  = blockIdx.x * BN;
    const int m0  = blockIdx.y * BM;
    const int tid = threadIdx.x;
    const int tr  = tid / 16;
    const int tc  = tid % 16;

    const int a_row0 = (tid)       >> 2, a_kq0 = (tid)       & 3;
    const int a_row1 = (tid + 256) >> 2, a_kq1 = (tid + 256) & 3;
    const int w_row  = tid >> 2,         w_kq  = tid & 3;

    float acc[8][4];
#pragma unroll
    for (int i = 0; i < 8; i++)
#pragma unroll
        for (int j = 0; j < 4; j++) acc[i][j] = 0.f;

    float4 a0, a1, wv;

    // prologue: tile 0
    a0 = *(const float4*)&x[(size_t)(m0 + a_row0) * II + a_kq0 * 4];
    a1 = *(const float4*)&x[(size_t)(m0 + a_row1) * II + a_kq1 * 4];
    wv = *(const float4*)&Wih[(size_t)(n0 + w_row) * II + w_kq * 4];
    As[0][a_kq0*4+0][a_row0] = a0.x; As[0][a_kq0*4+1][a_row0] = a0.y;
    As[0][a_kq0*4+2][a_row0] = a0.z; As[0][a_kq0*4+3][a_row0] = a0.w;
    As[0][a_kq1*4+0][a_row1] = a1.x; As[0][a_kq1*4+1][a_row1] = a1.y;
    As[0][a_kq1*4+2][a_row1] = a1.z; As[0][a_kq1*4+3][a_row1] = a1.w;
    Ws[0][w_kq*4+0][w_row]   = wv.x; Ws[0][w_kq*4+1][w_row]   = wv.y;
    Ws[0][w_kq*4+2][w_row]   = wv.z; Ws[0][w_kq*4+3][w_row]   = wv.w;
    __syncthreads();

    const int NIT = II / BKi; // 16
    for (int it = 0; it < NIT; it++) {
        const int cur = it & 1;
        if (it + 1 < NIT) {
            const int k0 = (it + 1) * BKi;
            a0 = *(const float4*)&x[(size_t)(m0 + a_row0) * II + k0 + a_kq0 * 4];
            a1 = *(const float4*)&x[(size_t)(m0 + a_row1) * II + k0 + a_kq1 * 4];
            wv = *(const float4*)&Wih[(size_t)(n0 + w_row) * II + k0 + w_kq * 4];
        }
#pragma unroll
        for (int kk = 0; kk < 16; kk++) {
            float a[8], w[4];
#pragma unroll
            for (int i = 0; i < 8; i++) a[i] = As[cur][kk][tr * 8 + i];
#pragma unroll
            for (int j = 0; j < 4; j++) w[j] = Ws[cur][kk][tc * 4 + j];
#pragma unroll
            for (int i = 0; i < 8; i++)
#pragma unroll
                for (int j = 0; j < 4; j++) acc[i][j] += a[i] * w[j];
        }
        if (it + 1 < NIT) {
            const int nxt = cur ^ 1;
            As[nxt][a_kq0*4+0][a_row0] = a0.x; As[nxt][a_kq0*4+1][a_row0] = a0.y;
            As[nxt][a_kq0*4+2][a_row0] = a0.z; As[nxt][a_kq0*4+3][a_row0] = a0.w;
            As[nxt][a_kq1*4+0][a_row1] = a1.x; As[nxt][a_kq1*4+1][a_row1] = a1.y;
            As[nxt][a_kq1*4+2][a_row1] = a1.z; As[nxt][a_kq1*4+3][a_row1] = a1.w;
            Ws[nxt][w_kq*4+0][w_row]   = wv.x; Ws[nxt][w_kq*4+1][w_row]   = wv.y;
            Ws[nxt][w_kq*4+2][w_row]   = wv.z; Ws[nxt][w_kq*4+3][w_row]   = wv.w;
        }
        __syncthreads();
    }

    const float4 bv = *(const float4*)&bih[n0 + tc * 4];
#pragma unroll
    for (int i = 0; i < 8; i++) {
        const size_t row = (size_t)(m0 + tr * 8 + i);
        float4 o;
        o.x = acc[i][0] + bv.x; o.y = acc[i][1] + bv.y;
        o.z = acc[i][2] + bv.z; o.w = acc[i][3] + bv.w;
        *(float4*)&g_xg[row * G4 + (n0 + tc * 4)] = o;
    }
}

// =====================================================================
// device-wide barrier
// =====================================================================
__device__ __forceinline__ void grid_sync_()
{
    __threadfence();
    __syncthreads();
    if (threadIdx.x == 0) {
        const unsigned gen = g_bar_gen;
        if (atomicAdd(&g_bar_count, 1u) == (unsigned)gridDim.x - 1u) {
            g_bar_count = 0;
            __threadfence();
            g_bar_gen = gen + 1u;
        } else {
            while (g_bar_gen == gen) { __nanosleep(64); }
        }
        __threadfence();
    }
    __syncthreads();
}

// =====================================================================
// Persistent LSTM recurrence: split-bf16 tensor-core GEMM via WMMA.
// 128 CTAs x 256 thr; CTA owns 32 output cols (4 gates x 8 units).
// W_hh slice (hi+lo bf16, 132 KB) smem-resident for all 512 steps.
// D[64,32] per step: 8 warps, each one 16x16 tile, 3 mma per kstep
// (Ah*Bh + Ah*Bl + Al*Bh), fp32 accumulate.
// =====================================================================
__global__ __launch_bounds__(256) void lstm_persistent(const float* __restrict__ Whh,
                                                       const float* __restrict__ bhh)
{
    extern __shared__ char smraw[];
    __nv_bfloat16* BsH = (__nv_bfloat16*)(smraw + SMB_BSH);
    __nv_bfloat16* BsL = (__nv_bfloat16*)(smraw + SMB_BSL);
    __nv_bfloat16* AsH = (__nv_bfloat16*)(smraw + SMB_ASH);
    __nv_bfloat16* AsL = (__nv_bfloat16*)(smraw + SMB_ASL);
    float* Gs = (float*)(smraw + SMB_GS);
    float* Cs = (float*)(smraw + SMB_CS);
    float* Bh = (float*)(smraw + SMB_BH);

    const int tid  = threadIdx.x;
    const int warp = tid >> 5;
    const int u0   = blockIdx.x * 8;       // first hidden unit owned by this CTA

    // ---- one-time: split W_hh slice into smem hi/lo bf16 ----
    // local col c (0..31): gate g = c>>3, unit = u0 + (c&7)
    // B layout: element (k, c) at Bs[c*BPITCH + k]  (col-major for wmma matrix_b)
    {
        const int c  = tid >> 3;
        const int e8 = tid & 7;
        const int grow = (c >> 3) * HH + u0 + (c & 7);
        const float* wr = Whh + (size_t)grow * HH;
        for (int q = 0; q < 32; q++) {
            const int k = e8 * 128 + q * 4;
            const float4 v = *(const float4*)(wr + k);
            const __nv_bfloat16 b0 = __float2bfloat16(v.x);
            const __nv_bfloat16 b1 = __float2bfloat16(v.y);
            const __nv_bfloat16 b2 = __float2bfloat16(v.z);
            const __nv_bfloat16 b3 = __float2bfloat16(v.w);
            BsH[c * BPITCH + k + 0] = b0;
            BsH[c * BPITCH + k + 1] = b1;
            BsH[c * BPITCH + k + 2] = b2;
            BsH[c * BPITCH + k + 3] = b3;
            BsL[c * BPITCH + k + 0] = __float2bfloat16(v.x - __bfloat162float(b0));
            BsL[c * BPITCH + k + 1] = __float2bfloat16(v.y - __bfloat162float(b1));
            BsL[c * BPITCH + k + 2] = __float2bfloat16(v.z - __bfloat162float(b2));
            BsL[c * BPITCH + k + 3] = __float2bfloat16(v.w - __bfloat162float(b3));
        }
    }
    if (tid < 32) Bh[tid] = bhh[(tid >> 3) * HH + u0 + (tid & 7)];
    for (int i = tid; i < 64 * 8; i += 256) Cs[i] = 0.f;
    __syncthreads();

    // warp tile: wm in 0..3 (M rows wm*16), wn in 0..1 (N cols wn*16)
    const int wm = warp & 3;
    const int wn = warp >> 2;

    // A-staging role: 4 threads per batch row, each copies 2x uint4 per part
    const int cp_row = tid >> 2;           // 0..63
    const int cp_q   = tid & 3;            // 0..3 -> uint4 chunks cp_q*2, cp_q*2+1

    // pointwise role
    const int pb = tid >> 2;               // batch 0..63
    const int pu = (tid & 3) * 2;          // unit pair 0,2,4,6

    for (int t = 0; t < TT; t++) {
        wmma::fragment<wmma::accumulator, 16, 16, 16, float> facc;
        wmma::fill_fragment(facc, 0.0f);

        if (t > 0) {
            const __nv_bfloat16* hHp = g_hhi + (size_t)(t - 1) * BB * HH;
            const __nv_bfloat16* hLp = g_hlo + (size_t)(t - 1) * BB * HH;
            const size_t rbase = (size_t)cp_row * HH + cp_q * 16;   // two uint4 = 16 bf16

            uint4 rh0 = *(const uint4*)(hHp + rbase);
            uint4 rh1 = *(const uint4*)(hHp + rbase + 8);
            uint4 rl0 = *(const uint4*)(hLp + rbase);
            uint4 rl1 = *(const uint4*)(hLp + rbase + 8);
            {
                const int so = cp_row * APITCH + cp_q * 16;
                *(uint4*)(AsH + so)     = rh0;
                *(uint4*)(AsH + so + 8) = rh1;
                *(uint4*)(AsL + so)     = rl0;
                *(uint4*)(AsL + so + 8) = rl1;
            }
            __syncthreads();

            for (int kt = 0; kt < 16; kt++) {          // 16 chunks of KCH=64
                const int buf = kt & 1;
                if (kt < 15) {
                    const size_t ro = rbase + (size_t)(kt + 1) * KCH;
                    rh0 = *(const uint4*)(hHp + ro);
                    rh1 = *(const uint4*)(hHp + ro + 8);
                    rl0 = *(const uint4*)(hLp + ro);
                    rl1 = *(const uint4*)(hLp + ro + 8);
                }

                const __nv_bfloat16* aH = AsH + buf * 64 * APITCH + wm * 16 * APITCH;
                const __nv_bfloat16* aL = AsL + buf * 64 * APITCH + wm * 16 * APITCH;
                const __nv_bfloat16* bH = BsH + wn * 16 * BPITCH + kt * KCH;
                const __nv_bfloat16* bL = BsL + wn * 16 * BPITCH + kt * KCH;

#pragma unroll
                for (int ks = 0; ks < 4; ks++) {       // 4 k-steps of 16 per chunk
                    wmma::fragment<wmma::matrix_a, 16, 16, 16, __nv_bfloat16, wmma::row_major> faH;
                    wmma::fragment<wmma::matrix_a, 16, 16, 16, __nv_bfloat16, wmma::row_major> faL;
                    wmma::fragment<wmma::matrix_b, 16, 16, 16, __nv_bfloat16, wmma::col_major> fbH;
                    wmma::fragment<wmma::matrix_b, 16, 16, 16, __nv_bfloat16, wmma::col_major> fbL;
                    wmma::load_matrix_sync(faH, aH + ks * 16, APITCH);
                    wmma::load_matrix_sync(faL, aL + ks * 16, APITCH);
                    wmma::load_matrix_sync(fbH, bH + ks * 16, BPITCH);
                    wmma::load_matrix_sync(fbL, bL + ks * 16, BPITCH);
                    wmma::mma_sync(facc, faH, fbH, facc);
                    wmma::mma_sync(facc, faH, fbL, facc);
                    wmma::mma_sync(facc, faL, fbH, facc);
                }

                if (kt < 15) {
                    const int so = (buf ^ 1) * 64 * APITCH + cp_row * APITCH + cp_q * 16;
                    *(uint4*)(AsH + so)     = rh0;
                    *(uint4*)(AsH + so + 8) = rh1;
                    *(uint4*)(AsL + so)     = rl0;
                    *(uint4*)(AsL + so + 8) = rl1;
                }
                __syncthreads();
            }
        }

        // ---- store D tile to Gs [64 rows][pitch 40] ----
        wmma::store_matrix_sync(Gs + wm * 16 * 40 + wn * 16, facc, 40, wmma::mem_row_major);
        __syncthreads();

        // ---- pointwise: gates -> c,h; write h as bf16 hi/lo ----
        {
            const size_t xbase = ((size_t)pb * TT + t) * G4 + u0 + pu;
            const float2 vxi = *(const float2*)(g_xg + xbase);
            const float2 vxf = *(const float2*)(g_xg + xbase + HH);
            const float2 vxg = *(const float2*)(g_xg + xbase + 2 * HH);
            const float2 vxo = *(const float2*)(g_xg + xbase + 3 * HH);

            const float2 vri = *(const float2*)(Gs + pb * 40 + 0  + pu);
            const float2 vrf = *(const float2*)(Gs + pb * 40 + 8  + pu);
            const float2 vrg = *(const float2*)(Gs + pb * 40 + 16 + pu);
            const float2 vro = *(const float2*)(Gs + pb * 40 + 24 + pu);

            const float2 vcp = *(const float2*)(Cs + pb * 8 + pu);

            const float i0 = 1.f / (1.f + expf(-(vxi.x + vri.x + Bh[pu])));
            const float f0 = 1.f / (1.f + expf(-(vxf.x + vrf.x + Bh[8 + pu])));
            const float g0 = tanhf(vxg.x + vrg.x + Bh[16 + pu]);
            const float o0 = 1.f / (1.f + expf(-(vxo.x + vro.x + Bh[24 + pu])));
            const float c0 = f0 * vcp.x + i0 * g0;
            const float h0 = o0 * tanhf(c0);

            const float i1 = 1.f / (1.f + expf(-(vxi.y + vri.y + Bh[pu + 1])));
            const float f1 = 1.f / (1.f + expf(-(vxf.y + vrf.y + Bh[9 + pu])));
            const float g1 = tanhf(vxg.y + vrg.y + Bh[17 + pu]);
            const float o1 = 1.f / (1.f + expf(-(vxo.y + vro.y + Bh[25 + pu])));
            const float c1 = f1 * vcp.y + i1 * g1;
            const float h1 = o1 * tanhf(c1);

            *(float2*)(Cs + pb * 8 + pu) = make_float2(c0, c1);

            const __nv_bfloat16 h0h = __float2bfloat16(h0);
            const __nv_bfloat16 h1h = __float2bfloat16(h1);
            const __nv_bfloat16 h0l = __float2bfloat16(h0 - __bfloat162float(h0h));
            const __nv_bfloat16 h1l = __float2bfloat16(h1 - __bfloat162float(h1h));

            const size_t hidx = ((size_t)t * BB + pb) * HH + u0 + pu;
            g_hhi[hidx]     = h0h;
            g_hhi[hidx + 1] = h1h;
            g_hlo[hidx]     = h0l;
            g_hlo[hidx + 1] = h1l;
        }

        grid_sync_();
    }
}

// =====================================================================
// FC: out[b][t] = dot(h_t[b], W_fc) + b_fc   (h = hi + lo)
// =====================================================================
__global__ __launch_bounds__(128) void fc_kernel(const float* __restrict__ Wfc,
                                                 const float* __restrict__ bfc,
                                                 float* __restrict__ out)
{
    const int bt = blockIdx.x;
    const int t  = bt >> 6;
    const int b  = bt & 63;
    const size_t base = ((size_t)t * BB + b) * HH;
    const int tid = threadIdx.x;

    float s = 0.f;
#pragma unroll
    for (int q = 0; q < 8; q++) {
        const int j = tid + q * 128;
        const float h = __bfloat162float(g_hhi[base + j]) + __bfloat162float(g_hlo[base + j]);
        s += h * Wfc[j];
    }
#pragma unroll
    for (int off = 16; off; off >>= 1) s += __shfl_down_sync(0xffffffffu, s, off);

    __shared__ float red[4];
    if ((tid & 31) == 0) red[tid >> 5] = s;
    __syncthreads();
    if (tid == 0)
        out[(size_t)b * TT + t] = red[0] + red[1] + red[2] + red[3] + bfc[0];
}

// =====================================================================
extern "C" void kernel_launch(void* const* d_in, const int* in_sizes, int n_in,
                              void* d_out, int out_size)
{
    const float* x   = (const float*)d_in[0];
    const float* Wih = (const float*)d_in[1];
    const float* Whh = (const float*)d_in[2];
    const float* bih = (const float*)d_in[3];
    const float* bhh = (const float*)d_in[4];
    const float* Wfc = (const float*)d_in[5];
    const float* bfc = (const float*)d_in[6];
    float* out = (float*)d_out;

    cudaFuncSetAttribute(lstm_persistent,
                         cudaFuncAttributeMaxDynamicSharedMemorySize, (int)SMB_TOT);

    // 1) input projection (one GEMM)
    xg_gemm<<<dim3(G4 / 64, MM / 128), 256>>>(x, Wih, bih);

    // 2) full recurrence: one persistent tensor-core kernel
    lstm_persistent<<<NCTA, 256, SMB_TOT>>>(Whh, bhh);

    // 3) output projection
    fc_kernel<<<MM, 128>>>(Wfc, bfc, out);
}